// round 10
// baseline (speedup 1.0000x reference)
#include <cuda_runtime.h>
#include <cuda_bf16.h>
#include <cuda_fp16.h>
#include <cstdint>

#define SRC_LEN 256
#define TRG_LEN 256
#define BATCH   32
#define HID     512
#define ATT     128

// Scratch for projected activations. Layout: [(len_idx * BATCH + b) * ATT + a]
__device__ float g_enc_att[SRC_LEN * BATCH * ATT];
__device__ float g_dec_att[TRG_LEN * BATCH * ATT];

// Precomputed, pre-swizzled bf16 hi/lo W tiles: [z][chunk][16KB tile]
__device__ __align__(16) unsigned char g_wh[2][8][16384];
__device__ __align__(16) unsigned char g_wl[2][8][16384];

typedef unsigned int u32;
typedef unsigned long long u64;

__device__ __forceinline__ u32 smem_u32(const void* p) {
    u32 a; asm("{ .reg .u64 t; cvta.to.shared.u64 t, %1; cvt.u32.u64 %0, t; }"
               : "=r"(a) : "l"(p));
    return a;
}

#define LDSM_X4(rr, addr) \
    asm volatile("ldmatrix.sync.aligned.m8n8.x4.shared.b16 {%0,%1,%2,%3}, [%4];" \
        : "=r"((rr)[0]), "=r"((rr)[1]), "=r"((rr)[2]), "=r"((rr)[3]) : "r"(addr))

__device__ __forceinline__ void mma16816(float* d, const u32* a, const u32* b) {
    asm volatile(
        "mma.sync.aligned.m16n8k16.row.col.f32.bf16.bf16.f32 "
        "{%0,%1,%2,%3}, {%4,%5,%6,%7}, {%8,%9}, {%0,%1,%2,%3};"
        : "+f"(d[0]), "+f"(d[1]), "+f"(d[2]), "+f"(d[3])
        : "r"(a[0]), "r"(a[1]), "r"(a[2]), "r"(a[3]), "r"(b[0]), "r"(b[1]));
}

__device__ __forceinline__ void cp16(u32 smem_dst, const void* gsrc) {
    asm volatile("cp.async.cg.shared.global [%0], [%1], 16;"
                 :: "r"(smem_dst), "l"(gsrc) : "memory");
}
#define CP_COMMIT()  asm volatile("cp.async.commit_group;" ::: "memory")
#define CP_WAIT(n)   asm volatile("cp.async.wait_group %0;" :: "n"(n) : "memory")

// fp32 pair -> bf16 hi pair (truncate, via PRMT) + bf16 lo pair (residual, rn).
__device__ __forceinline__ void split2(float x0, float x1, u32& h2, u32& l2) {
    const u32 b0 = __float_as_uint(x0), b1 = __float_as_uint(x1);
    asm("prmt.b32 %0, %1, %2, 0x7632;" : "=r"(h2) : "r"(b0), "r"(b1));
    const float lf0 = x0 - __uint_as_float(b0 & 0xFFFF0000u);
    const float lf1 = x1 - __uint_as_float(b1 & 0xFFFF0000u);
    __nv_bfloat162 t = __float22bfloat162_rn(make_float2(lf0, lf1));
    l2 = *reinterpret_cast<u32*>(&t);
}
__device__ __forceinline__ void split_f4x2(const float4 v0, const float4 v1,
                                           uint4& H, uint4& L) {
    split2(v0.x, v0.y, H.x, L.x);
    split2(v0.z, v0.w, H.y, L.y);
    split2(v1.x, v1.y, H.z, L.z);
    split2(v1.z, v1.w, H.w, L.w);
}

// =====================================================================
// prep_w: split W_s / W_t into bf16 hi/lo, stored pre-swizzled per 64-k
// chunk. grid = (64 [chunk*8+slice], 2 z), 128 threads, 1 unit each.
// =====================================================================
__global__ __launch_bounds__(128) void prep_w_kernel(
    const float* __restrict__ W_s, const float* __restrict__ W_t)
{
    const int c = blockIdx.x >> 3;
    const int slice = blockIdx.x & 7;
    const int z = blockIdx.y;
    const float* __restrict__ W = z ? W_t : W_s;
    const int pu = slice * 128 + threadIdx.x;   // 0..1023 pair-units
    const int row = pu >> 3;                    // 0..127
    const int qq = (pu & 7) << 1;               // even float4 index
    const float* p = W + (size_t)row * HID + c * 64 + (qq << 2);
    const float4 v0 = *reinterpret_cast<const float4*>(p);
    const float4 v1 = *reinterpret_cast<const float4*>(p + 4);
    uint4 H, L; split_f4x2(v0, v1, H, L);
    const u32 off = (u32)(row * 128 + 16 * ((pu & 7) ^ (row & 7)));
    *reinterpret_cast<uint4*>(&g_wh[z][c][off]) = H;
    *reinterpret_cast<uint4*>(&g_wl[z][c][off]) = L;
}

// =====================================================================
// HMMA projection (R9, measured ~18us): C = X * W^T (+ bias if z)
// =====================================================================
#define PSM_AH 0
#define PSM_AL 16384
#define PSM_B  32768          // stage s: BH @ PSM_B + s*32768, BL = BH + 16384
#define PSM_TOTAL 98304

__global__ __launch_bounds__(256) void proj_mma_kernel(
    const float* __restrict__ dec_out,
    const float* __restrict__ enc_outs,
    const float* __restrict__ b_t)
{
    extern __shared__ char smem[];
    const u32 sb = smem_u32(smem);
    const u32 AHs = sb + PSM_AH, ALs = sb + PSM_AL;

    const int tid = threadIdx.x;
    const int wid = tid >> 5;
    const int lane = tid & 31;
    const int z = blockIdx.y;
    const float* __restrict__ X = z ? dec_out : enc_outs;
    float* __restrict__ C = z ? g_dec_att : g_enc_att;
    const int m0 = blockIdx.x * 128;

    const int j = lane >> 3;
    const int r = lane & 7;
    const int wm = wid & 3;
    const int wn = wid >> 2;

    const int rowA0 = wm * 32 + ((j & 1) << 3) + r;
    const int rowA1 = rowA0 + 16;
    const u32 offA0 = rowA0 * 128, cxA0 = (rowA0 & 7) * 16;
    const u32 offA1 = rowA1 * 128, cxA1 = (rowA1 & 7) * 16;
    const u32 kbAj = (u32)((j >> 1) << 4);

    u32 offB[4], cxB[4];
    #pragma unroll
    for (int p = 0; p < 4; p++) {
        const int nrow = wn * 64 + p * 16 + ((j >> 1) << 3) + r;
        offB[p] = nrow * 128;
        cxB[p]  = (nrow & 7) * 16;
    }
    const u32 kbBj = (u32)((j & 1) << 4);

    float d[2][8][4];
    #pragma unroll
    for (int mf = 0; mf < 2; mf++)
        #pragma unroll
        for (int nf = 0; nf < 8; nf++)
            #pragma unroll
            for (int q = 0; q < 4; q++) d[mf][nf][q] = 0.f;

    // Issue B(0) copy into stage 0.
    {
        const unsigned char* sh = g_wh[z][0];
        const unsigned char* sl = g_wl[z][0];
        #pragma unroll
        for (int rr = 0; rr < 4; rr++) {
            const u32 off = (u32)((tid + rr * 256) << 4);
            cp16(sb + PSM_B + off, sh + off);
            cp16(sb + PSM_B + 16384 + off, sl + off);
        }
        CP_COMMIT();
    }
    // Preload A raw values for chunk 0.
    float4 areg[8];
    #pragma unroll
    for (int rr = 0; rr < 4; rr++) {
        const int pu = tid + rr * 256;
        const int row = pu >> 3;
        const int qq = (pu & 7) << 1;
        const float* p = X + (size_t)(m0 + row) * HID + (qq << 2);
        areg[2 * rr]     = *reinterpret_cast<const float4*>(p);
        areg[2 * rr + 1] = *reinterpret_cast<const float4*>(p + 4);
    }

    for (int c = 0; c < 8; c++) {
        __syncthreads();

        #pragma unroll
        for (int rr = 0; rr < 4; rr++) {
            const int pu = tid + rr * 256;
            const int row = pu >> 3;
            uint4 H, L; split_f4x2(areg[2 * rr], areg[2 * rr + 1], H, L);
            const u32 off = (u32)(row * 128 + 16 * ((pu & 7) ^ (row & 7)));
            *reinterpret_cast<uint4*>(smem + PSM_AH + off) = H;
            *reinterpret_cast<uint4*>(smem + PSM_AL + off) = L;
        }
        if (c < 7) {
            const u32 bs = sb + PSM_B + ((c + 1) & 1) * 32768;
            const unsigned char* sh = g_wh[z][c + 1];
            const unsigned char* sl = g_wl[z][c + 1];
            #pragma unroll
            for (int rr = 0; rr < 4; rr++) {
                const u32 off = (u32)((tid + rr * 256) << 4);
                cp16(bs + off, sh + off);
                cp16(bs + 16384 + off, sl + off);
            }
            CP_COMMIT();
            const int k0n = (c + 1) * 64;
            #pragma unroll
            for (int rr = 0; rr < 4; rr++) {
                const int pu = tid + rr * 256;
                const int row = pu >> 3;
                const int qq = (pu & 7) << 1;
                const float* p = X + (size_t)(m0 + row) * HID + k0n + (qq << 2);
                areg[2 * rr]     = *reinterpret_cast<const float4*>(p);
                areg[2 * rr + 1] = *reinterpret_cast<const float4*>(p + 4);
            }
            CP_WAIT(1);
        } else {
            CP_WAIT(0);
        }
        __syncthreads();

        const u32 BHs = sb + PSM_B + (c & 1) * 32768;
        const u32 BLs = BHs + 16384;

        #pragma unroll
        for (int kk = 0; kk < 4; kk++) {
            const u32 kbA = (u32)(kk * 32) + kbAj;
            const u32 kbB = (u32)(kk * 32) + kbBj;

            u32 ah0[4], ah1[4], al0[4], al1[4];
            LDSM_X4(ah0, AHs + offA0 + (kbA ^ cxA0));
            LDSM_X4(ah1, AHs + offA1 + (kbA ^ cxA1));
            LDSM_X4(al0, ALs + offA0 + (kbA ^ cxA0));
            LDSM_X4(al1, ALs + offA1 + (kbA ^ cxA1));

            u32 bb[4][4];
            #pragma unroll
            for (int p = 0; p < 4; p++)
                LDSM_X4(bb[p], BHs + offB[p] + (kbB ^ cxB[p]));
            #pragma unroll
            for (int p = 0; p < 4; p++) {
                mma16816(d[0][2 * p],     ah0, &bb[p][0]);
                mma16816(d[0][2 * p + 1], ah0, &bb[p][2]);
                mma16816(d[1][2 * p],     ah1, &bb[p][0]);
                mma16816(d[1][2 * p + 1], ah1, &bb[p][2]);
                mma16816(d[0][2 * p],     al0, &bb[p][0]);
                mma16816(d[0][2 * p + 1], al0, &bb[p][2]);
                mma16816(d[1][2 * p],     al1, &bb[p][0]);
                mma16816(d[1][2 * p + 1], al1, &bb[p][2]);
            }
            #pragma unroll
            for (int p = 0; p < 4; p++)
                LDSM_X4(bb[p], BLs + offB[p] + (kbB ^ cxB[p]));
            #pragma unroll
            for (int p = 0; p < 4; p++) {
                mma16816(d[0][2 * p],     ah0, &bb[p][0]);
                mma16816(d[0][2 * p + 1], ah0, &bb[p][2]);
                mma16816(d[1][2 * p],     ah1, &bb[p][0]);
                mma16816(d[1][2 * p + 1], ah1, &bb[p][2]);
            }
        }
    }

    const int er = lane >> 2;
    const int ec = (lane & 3) << 1;
    float bias[8][2];
    #pragma unroll
    for (int nf = 0; nf < 8; nf++) {
        const int col = wn * 64 + nf * 8 + ec;
        bias[nf][0] = z ? b_t[col] : 0.f;
        bias[nf][1] = z ? b_t[col + 1] : 0.f;
    }
    #pragma unroll
    for (int mf = 0; mf < 2; mf++) {
        const int row = m0 + wm * 32 + mf * 16 + er;
        #pragma unroll
        for (int nf = 0; nf < 8; nf++) {
            const int col = wn * 64 + nf * 8 + ec;
            float2 v0; v0.x = d[mf][nf][0] + bias[nf][0]; v0.y = d[mf][nf][1] + bias[nf][1];
            *reinterpret_cast<float2*>(C + (size_t)row * ATT + col) = v0;
            float2 v1; v1.x = d[mf][nf][2] + bias[nf][0]; v1.y = d[mf][nf][3] + bias[nf][1];
            *reinterpret_cast<float2*>(C + (size_t)(row + 8) * ATT + col) = v1;
        }
    }
}

// =====================================================================
// Score kernel with MUFU/FMA pipe splitting:
// 7/8 of a-steps use tanh.approx (MUFU); 1/8 use a clamped Pade(5,4)
// evaluated entirely on the FMA pipe (bit-hack reciprocal + 2 Newton).
// =====================================================================
__device__ __forceinline__ float tanh_fast(float x) {
    float y;
    asm("tanh.approx.f32 %0, %1;" : "=f"(y) : "f"(x));
    return y;
}

// Pade(5,4): tanh(x) ~= x(945+105t+t^2)/(945+420t+15t^2), t=x^2, |x|<=3.
// err <= ~4e-4 on [-3,3]; clamp tail err <= 4.5e-3 (rare, |x|>3).
__device__ __forceinline__ float tanh_pade(float x) {
    x = fminf(3.0f, fmaxf(-3.0f, x));
    const float t = x * x;
    const float num = fmaf(t, t + 105.0f, 945.0f);
    const float den = fmaf(t, fmaf(t, 15.0f, 420.0f), 945.0f);
    float r = __uint_as_float(0x7EF311C3u - __float_as_uint(den));
    r = r * fmaf(-den, r, 2.0f);
    r = r * fmaf(-den, r, 2.0f);
    return x * num * r;
}

__global__ __launch_bounds__(256) void score_kernel(
    const float* __restrict__ v_a,
    float* __restrict__ out)
{
    __shared__ float sh_e[ATT][33];
    __shared__ float sh_d[ATT][33];
    __shared__ float sh_v[ATT];

    const int tid = threadIdx.x;
    const int b = blockIdx.z;
    const int s_base = blockIdx.x * 32;
    const int t_base = blockIdx.y * 32;

    for (int idx = tid; idx < 32 * 32; idx += 256) {
        const int i  = idx >> 5;
        const int a4 = idx & 31;
        const float4 ev = *reinterpret_cast<const float4*>(
            g_enc_att + ((size_t)(s_base + i) * BATCH + b) * ATT + (a4 << 2));
        sh_e[a4 * 4 + 0][i] = ev.x;
        sh_e[a4 * 4 + 1][i] = ev.y;
        sh_e[a4 * 4 + 2][i] = ev.z;
        sh_e[a4 * 4 + 3][i] = ev.w;
        const float4 dv = *reinterpret_cast<const float4*>(
            g_dec_att + ((size_t)(t_base + i) * BATCH + b) * ATT + (a4 << 2));
        sh_d[a4 * 4 + 0][i] = dv.x;
        sh_d[a4 * 4 + 1][i] = dv.y;
        sh_d[a4 * 4 + 2][i] = dv.z;
        sh_d[a4 * 4 + 3][i] = dv.w;
    }
    if (tid < ATT) sh_v[tid] = v_a[tid];
    __syncthreads();

    const int tx = tid & 15;
    const int ty = tid >> 4;
    const int sl = tx << 1;
    const int tl = ty << 1;

    float acc00 = 0.f, acc01 = 0.f, acc10 = 0.f, acc11 = 0.f;

    #pragma unroll 8
    for (int a = 0; a < ATT; a++) {
        const float va = sh_v[a];
        const float e0 = sh_e[a][sl];
        const float e1 = sh_e[a][sl + 1];
        const float d0 = sh_d[a][tl];
        const float d1 = sh_d[a][tl + 1];
        if ((a & 7) == 4) {   // FMA-pipe path (compile-time resolved)
            acc00 = fmaf(va, tanh_pade(d0 + e0), acc00);
            acc01 = fmaf(va, tanh_pade(d0 + e1), acc01);
            acc10 = fmaf(va, tanh_pade(d1 + e0), acc10);
            acc11 = fmaf(va, tanh_pade(d1 + e1), acc11);
        } else {              // MUFU path
            acc00 = fmaf(va, tanh_fast(d0 + e0), acc00);
            acc01 = fmaf(va, tanh_fast(d0 + e1), acc01);
            acc10 = fmaf(va, tanh_fast(d1 + e0), acc10);
            acc11 = fmaf(va, tanh_fast(d1 + e1), acc11);
        }
    }

    const int tg = t_base + tl;
    const int sg = s_base + sl;
    float* o0 = out + ((size_t)tg * BATCH + b) * SRC_LEN + sg;
    float2 r0; r0.x = acc00; r0.y = acc01;
    *reinterpret_cast<float2*>(o0) = r0;
    float* o1 = o0 + (size_t)BATCH * SRC_LEN;
    float2 r1; r1.x = acc10; r1.y = acc11;
    *reinterpret_cast<float2*>(o1) = r1;
}

extern "C" void kernel_launch(void* const* d_in, const int* in_sizes, int n_in,
                              void* d_out, int out_size)
{
    const float* dec_out  = (const float*)d_in[0];  // (256, 32, 512)
    const float* enc_outs = (const float*)d_in[1];  // (256, 32, 512)
    const float* W_s      = (const float*)d_in[2];  // (128, 512)
    const float* W_t      = (const float*)d_in[3];  // (128, 512)
    const float* b_t      = (const float*)d_in[4];  // (128,)
    const float* v_a      = (const float*)d_in[5];  // (128, 1)
    float* out = (float*)d_out;                     // (256, 32, 256)

    (void)in_sizes; (void)n_in; (void)out_size;

    cudaFuncSetAttribute(proj_mma_kernel,
                         cudaFuncAttributeMaxDynamicSharedMemorySize, PSM_TOTAL);

    prep_w_kernel<<<dim3(64, 2), 128>>>(W_s, W_t);
    proj_mma_kernel<<<dim3(64, 2), 256, PSM_TOTAL>>>(dec_out, enc_outs, b_t);
    score_kernel<<<dim3(SRC_LEN / 32, TRG_LEN / 32, BATCH), 256>>>(v_a, out);
}

// round 11
// speedup vs baseline: 1.0251x; 1.0251x over previous
#include <cuda_runtime.h>
#include <cuda_bf16.h>
#include <cuda_fp16.h>
#include <cstdint>

#define SRC_LEN 256
#define TRG_LEN 256
#define BATCH   32
#define HID     512
#define ATT     128

// Scratch for projected activations. Layout: [(len_idx * BATCH + b) * ATT + a]
__device__ float g_enc_att[SRC_LEN * BATCH * ATT];
__device__ float g_dec_att[TRG_LEN * BATCH * ATT];

// Precomputed, pre-swizzled bf16 hi/lo W tiles: [z][chunk][16KB tile]
__device__ __align__(16) unsigned char g_wh[2][8][16384];
__device__ __align__(16) unsigned char g_wl[2][8][16384];

typedef unsigned int u32;
typedef unsigned long long u64;

__device__ __forceinline__ u32 smem_u32(const void* p) {
    u32 a; asm("{ .reg .u64 t; cvta.to.shared.u64 t, %1; cvt.u32.u64 %0, t; }"
               : "=r"(a) : "l"(p));
    return a;
}

#define LDSM_X4(rr, addr) \
    asm volatile("ldmatrix.sync.aligned.m8n8.x4.shared.b16 {%0,%1,%2,%3}, [%4];" \
        : "=r"((rr)[0]), "=r"((rr)[1]), "=r"((rr)[2]), "=r"((rr)[3]) : "r"(addr))

__device__ __forceinline__ void mma16816(float* d, const u32* a, const u32* b) {
    asm volatile(
        "mma.sync.aligned.m16n8k16.row.col.f32.bf16.bf16.f32 "
        "{%0,%1,%2,%3}, {%4,%5,%6,%7}, {%8,%9}, {%0,%1,%2,%3};"
        : "+f"(d[0]), "+f"(d[1]), "+f"(d[2]), "+f"(d[3])
        : "r"(a[0]), "r"(a[1]), "r"(a[2]), "r"(a[3]), "r"(b[0]), "r"(b[1]));
}

__device__ __forceinline__ void cp16(u32 smem_dst, const void* gsrc) {
    asm volatile("cp.async.cg.shared.global [%0], [%1], 16;"
                 :: "r"(smem_dst), "l"(gsrc) : "memory");
}
#define CP_COMMIT()  asm volatile("cp.async.commit_group;" ::: "memory")
#define CP_WAIT(n)   asm volatile("cp.async.wait_group %0;" :: "n"(n) : "memory")

// fp32 pair -> bf16 hi pair (truncate, via PRMT) + bf16 lo pair (residual, rn).
__device__ __forceinline__ void split2(float x0, float x1, u32& h2, u32& l2) {
    const u32 b0 = __float_as_uint(x0), b1 = __float_as_uint(x1);
    asm("prmt.b32 %0, %1, %2, 0x7632;" : "=r"(h2) : "r"(b0), "r"(b1));
    const float lf0 = x0 - __uint_as_float(b0 & 0xFFFF0000u);
    const float lf1 = x1 - __uint_as_float(b1 & 0xFFFF0000u);
    __nv_bfloat162 t = __float22bfloat162_rn(make_float2(lf0, lf1));
    l2 = *reinterpret_cast<u32*>(&t);
}
__device__ __forceinline__ void split_f4x2(const float4 v0, const float4 v1,
                                           uint4& H, uint4& L) {
    split2(v0.x, v0.y, H.x, L.x);
    split2(v0.z, v0.w, H.y, L.y);
    split2(v1.x, v1.y, H.z, L.z);
    split2(v1.z, v1.w, H.w, L.w);
}

// =====================================================================
// prep_w: split W_s / W_t into bf16 hi/lo, stored pre-swizzled per 64-k
// chunk. grid = (32 [chunk*4+slice], 2 z), 256 threads, 1 unit each.
// =====================================================================
__global__ __launch_bounds__(256) void prep_w_kernel(
    const float* __restrict__ W_s, const float* __restrict__ W_t)
{
    const int c = blockIdx.x >> 2;
    const int slice = blockIdx.x & 3;
    const int z = blockIdx.y;
    const float* __restrict__ W = z ? W_t : W_s;
    const int pu = slice * 256 + threadIdx.x;   // 0..1023 pair-units
    const int row = pu >> 3;                    // 0..127
    const int qq = (pu & 7) << 1;               // even float4 index
    const float* p = W + (size_t)row * HID + c * 64 + (qq << 2);
    const float4 v0 = *reinterpret_cast<const float4*>(p);
    const float4 v1 = *reinterpret_cast<const float4*>(p + 4);
    uint4 H, L; split_f4x2(v0, v1, H, L);
    const u32 off = (u32)(row * 128 + 16 * ((pu & 7) ^ (row & 7)));
    *reinterpret_cast<uint4*>(&g_wh[z][c][off]) = H;
    *reinterpret_cast<uint4*>(&g_wl[z][c][off]) = L;
}

// =====================================================================
// HMMA projection: C[m][n] = sum_h X[m][h] * W[n][h]  (+ bias if z)
// BM=64: CTA = 64 m x 128 n; K-chunks of 64; bf16 hi/lo split, 3 passes.
// 8 warps = 2m x 4n, warp tile 32x32, mma.m16n8k16.
// 80KB smem -> 2 CTAs/SM: one CTA's fill overlaps the other's mma.
// grid = (128 m-tiles, 2 [enc|dec]), 256 threads.
// =====================================================================
#define PSM_AH 0
#define PSM_AL 8192
#define PSM_B  16384          // stage s: BH @ PSM_B + s*32768, BL = BH + 16384
#define PSM_TOTAL 81920

__global__ __launch_bounds__(256) void proj_mma_kernel(
    const float* __restrict__ dec_out,
    const float* __restrict__ enc_outs,
    const float* __restrict__ b_t)
{
    extern __shared__ char smem[];
    const u32 sb = smem_u32(smem);
    const u32 AHs = sb + PSM_AH, ALs = sb + PSM_AL;

    const int tid = threadIdx.x;
    const int wid = tid >> 5;
    const int lane = tid & 31;
    const int z = blockIdx.y;
    const float* __restrict__ X = z ? dec_out : enc_outs;
    float* __restrict__ C = z ? g_dec_att : g_enc_att;
    const int m0 = blockIdx.x * 64;

    // ldmatrix lane geometry
    const int j = lane >> 3;
    const int r = lane & 7;
    const int wm = wid & 1;        // m-group (x32)
    const int wn = wid >> 1;       // n-group (x32)

    const int rowA0 = wm * 32 + ((j & 1) << 3) + r;
    const int rowA1 = rowA0 + 16;
    const u32 offA0 = rowA0 * 128, cxA0 = (rowA0 & 7) * 16;
    const u32 offA1 = rowA1 * 128, cxA1 = (rowA1 & 7) * 16;
    const u32 kbAj = (u32)((j >> 1) << 4);

    u32 offB[2], cxB[2];
    #pragma unroll
    for (int p = 0; p < 2; p++) {
        const int nrow = wn * 32 + p * 16 + ((j >> 1) << 3) + r;
        offB[p] = nrow * 128;
        cxB[p]  = (nrow & 7) * 16;
    }
    const u32 kbBj = (u32)((j & 1) << 4);

    float d[2][4][4];
    #pragma unroll
    for (int mf = 0; mf < 2; mf++)
        #pragma unroll
        for (int nf = 0; nf < 4; nf++)
            #pragma unroll
            for (int q = 0; q < 4; q++) d[mf][nf][q] = 0.f;

    // Issue B(0) copy into stage 0.
    {
        const unsigned char* sh = g_wh[z][0];
        const unsigned char* sl = g_wl[z][0];
        #pragma unroll
        for (int rr = 0; rr < 4; rr++) {
            const u32 off = (u32)((tid + rr * 256) << 4);
            cp16(sb + PSM_B + off, sh + off);
            cp16(sb + PSM_B + 16384 + off, sl + off);
        }
        CP_COMMIT();
    }
    // Preload A raw values for chunk 0: 512 pair-units, 2 per thread.
    float4 areg[4];
    #pragma unroll
    for (int rr = 0; rr < 2; rr++) {
        const int pu = tid + rr * 256;
        const int row = pu >> 3;            // 0..63
        const int qq = (pu & 7) << 1;
        const float* p = X + (size_t)(m0 + row) * HID + (qq << 2);
        areg[2 * rr]     = *reinterpret_cast<const float4*>(p);
        areg[2 * rr + 1] = *reinterpret_cast<const float4*>(p + 4);
    }

    for (int c = 0; c < 8; c++) {
        __syncthreads();   // chunk c-1 ldmatrix done: A smem + B stage (c+1)&1 free

        // A: convert preloaded regs, STS.128.
        #pragma unroll
        for (int rr = 0; rr < 2; rr++) {
            const int pu = tid + rr * 256;
            const int row = pu >> 3;
            uint4 H, L; split_f4x2(areg[2 * rr], areg[2 * rr + 1], H, L);
            const u32 off = (u32)(row * 128 + 16 * ((pu & 7) ^ (row & 7)));
            *reinterpret_cast<uint4*>(smem + PSM_AH + off) = H;
            *reinterpret_cast<uint4*>(smem + PSM_AL + off) = L;
        }
        if (c < 7) {
            // Issue B(c+1) into the other stage (flies under mma below).
            const u32 bs = sb + PSM_B + ((c + 1) & 1) * 32768;
            const unsigned char* sh = g_wh[z][c + 1];
            const unsigned char* sl = g_wl[z][c + 1];
            #pragma unroll
            for (int rr = 0; rr < 4; rr++) {
                const u32 off = (u32)((tid + rr * 256) << 4);
                cp16(bs + off, sh + off);
                cp16(bs + 16384 + off, sl + off);
            }
            CP_COMMIT();
            // Preload next chunk's A (LDG latency hidden under mma below).
            const int k0n = (c + 1) * 64;
            #pragma unroll
            for (int rr = 0; rr < 2; rr++) {
                const int pu = tid + rr * 256;
                const int row = pu >> 3;
                const int qq = (pu & 7) << 1;
                const float* p = X + (size_t)(m0 + row) * HID + k0n + (qq << 2);
                areg[2 * rr]     = *reinterpret_cast<const float4*>(p);
                areg[2 * rr + 1] = *reinterpret_cast<const float4*>(p + 4);
            }
            CP_WAIT(1);    // B(c) done; B(c+1) still in flight
        } else {
            CP_WAIT(0);    // last chunk: B(7) done
        }
        __syncthreads();

        const u32 BHs = sb + PSM_B + (c & 1) * 32768;
        const u32 BLs = BHs + 16384;

        #pragma unroll
        for (int kk = 0; kk < 4; kk++) {
            const u32 kbA = (u32)(kk * 32) + kbAj;
            const u32 kbB = (u32)(kk * 32) + kbBj;

            u32 ah0[4], ah1[4], al0[4], al1[4];
            LDSM_X4(ah0, AHs + offA0 + (kbA ^ cxA0));
            LDSM_X4(ah1, AHs + offA1 + (kbA ^ cxA1));
            LDSM_X4(al0, ALs + offA0 + (kbA ^ cxA0));
            LDSM_X4(al1, ALs + offA1 + (kbA ^ cxA1));

            u32 bb[2][4];
            #pragma unroll
            for (int p = 0; p < 2; p++)
                LDSM_X4(bb[p], BHs + offB[p] + (kbB ^ cxB[p]));
            #pragma unroll
            for (int p = 0; p < 2; p++) {
                // hh pass
                mma16816(d[0][2 * p],     ah0, &bb[p][0]);
                mma16816(d[0][2 * p + 1], ah0, &bb[p][2]);
                mma16816(d[1][2 * p],     ah1, &bb[p][0]);
                mma16816(d[1][2 * p + 1], ah1, &bb[p][2]);
                // lh pass (A_lo x B_hi)
                mma16816(d[0][2 * p],     al0, &bb[p][0]);
                mma16816(d[0][2 * p + 1], al0, &bb[p][2]);
                mma16816(d[1][2 * p],     al1, &bb[p][0]);
                mma16816(d[1][2 * p + 1], al1, &bb[p][2]);
            }
            #pragma unroll
            for (int p = 0; p < 2; p++)
                LDSM_X4(bb[p], BLs + offB[p] + (kbB ^ cxB[p]));
            #pragma unroll
            for (int p = 0; p < 2; p++) {
                // hl pass (A_hi x B_lo)
                mma16816(d[0][2 * p],     ah0, &bb[p][0]);
                mma16816(d[0][2 * p + 1], ah0, &bb[p][2]);
                mma16816(d[1][2 * p],     ah1, &bb[p][0]);
                mma16816(d[1][2 * p + 1], ah1, &bb[p][2]);
            }
        }
    }

    // Epilogue: C frag (m16n8): c0,c1 -> row = lane/4, cols (lane%4)*2 +{0,1};
    // c2,c3 -> row+8. Add bias for dec, float2 stores.
    const int er = lane >> 2;
    const int ec = (lane & 3) << 1;
    float bias[4][2];
    #pragma unroll
    for (int nf = 0; nf < 4; nf++) {
        const int col = wn * 32 + nf * 8 + ec;
        bias[nf][0] = z ? b_t[col] : 0.f;
        bias[nf][1] = z ? b_t[col + 1] : 0.f;
    }
    #pragma unroll
    for (int mf = 0; mf < 2; mf++) {
        const int row = m0 + wm * 32 + mf * 16 + er;
        #pragma unroll
        for (int nf = 0; nf < 4; nf++) {
            const int col = wn * 32 + nf * 8 + ec;
            float2 v0; v0.x = d[mf][nf][0] + bias[nf][0]; v0.y = d[mf][nf][1] + bias[nf][1];
            *reinterpret_cast<float2*>(C + (size_t)row * ATT + col) = v0;
            float2 v1; v1.x = d[mf][nf][2] + bias[nf][0]; v1.y = d[mf][nf][3] + bias[nf][1];
            *reinterpret_cast<float2*>(C + (size_t)(row + 8) * ATT + col) = v1;
        }
    }
}

// =====================================================================
// Score kernel (pure MUFU f32 — proven at the MUFU element roofline):
// out[t][b][s] = sum_a v[a] * tanh(dec_att[t,b,a] + enc_att[s,b,a])
// =====================================================================
__device__ __forceinline__ float tanh_fast(float x) {
    float y;
    asm("tanh.approx.f32 %0, %1;" : "=f"(y) : "f"(x));
    return y;
}

__global__ __launch_bounds__(256) void score_kernel(
    const float* __restrict__ v_a,
    float* __restrict__ out)
{
    __shared__ float sh_e[ATT][33];
    __shared__ float sh_d[ATT][33];
    __shared__ float sh_v[ATT];

    const int tid = threadIdx.x;
    const int b = blockIdx.z;
    const int s_base = blockIdx.x * 32;
    const int t_base = blockIdx.y * 32;

    for (int idx = tid; idx < 32 * 32; idx += 256) {
        const int i  = idx >> 5;
        const int a4 = idx & 31;
        const float4 ev = *reinterpret_cast<const float4*>(
            g_enc_att + ((size_t)(s_base + i) * BATCH + b) * ATT + (a4 << 2));
        sh_e[a4 * 4 + 0][i] = ev.x;
        sh_e[a4 * 4 + 1][i] = ev.y;
        sh_e[a4 * 4 + 2][i] = ev.z;
        sh_e[a4 * 4 + 3][i] = ev.w;
        const float4 dv = *reinterpret_cast<const float4*>(
            g_dec_att + ((size_t)(t_base + i) * BATCH + b) * ATT + (a4 << 2));
        sh_d[a4 * 4 + 0][i] = dv.x;
        sh_d[a4 * 4 + 1][i] = dv.y;
        sh_d[a4 * 4 + 2][i] = dv.z;
        sh_d[a4 * 4 + 3][i] = dv.w;
    }
    if (tid < ATT) sh_v[tid] = v_a[tid];
    __syncthreads();

    const int tx = tid & 15;
    const int ty = tid >> 4;
    const int sl = tx << 1;
    const int tl = ty << 1;

    float acc00 = 0.f, acc01 = 0.f, acc10 = 0.f, acc11 = 0.f;

    #pragma unroll 4
    for (int a = 0; a < ATT; a++) {
        const float va = sh_v[a];
        const float e0 = sh_e[a][sl];
        const float e1 = sh_e[a][sl + 1];
        const float d0 = sh_d[a][tl];
        const float d1 = sh_d[a][tl + 1];
        acc00 = fmaf(va, tanh_fast(d0 + e0), acc00);
        acc01 = fmaf(va, tanh_fast(d0 + e1), acc01);
        acc10 = fmaf(va, tanh_fast(d1 + e0), acc10);
        acc11 = fmaf(va, tanh_fast(d1 + e1), acc11);
    }

    const int tg = t_base + tl;
    const int sg = s_base + sl;
    float* o0 = out + ((size_t)tg * BATCH + b) * SRC_LEN + sg;
    float2 r0; r0.x = acc00; r0.y = acc01;
    *reinterpret_cast<float2*>(o0) = r0;
    float* o1 = o0 + (size_t)BATCH * SRC_LEN;
    float2 r1; r1.x = acc10; r1.y = acc11;
    *reinterpret_cast<float2*>(o1) = r1;
}

extern "C" void kernel_launch(void* const* d_in, const int* in_sizes, int n_in,
                              void* d_out, int out_size)
{
    const float* dec_out  = (const float*)d_in[0];  // (256, 32, 512)
    const float* enc_outs = (const float*)d_in[1];  // (256, 32, 512)
    const float* W_s      = (const float*)d_in[2];  // (128, 512)
    const float* W_t      = (const float*)d_in[3];  // (128, 512)
    const float* b_t      = (const float*)d_in[4];  // (128,)
    const float* v_a      = (const float*)d_in[5];  // (128, 1)
    float* out = (float*)d_out;                     // (256, 32, 256)

    (void)in_sizes; (void)n_in; (void)out_size;

    cudaFuncSetAttribute(proj_mma_kernel,
                         cudaFuncAttributeMaxDynamicSharedMemorySize, PSM_TOTAL);

    prep_w_kernel<<<dim3(32, 2), 256>>>(W_s, W_t);
    proj_mma_kernel<<<dim3(128, 2), 256, PSM_TOTAL>>>(dec_out, enc_outs, b_t);
    score_kernel<<<dim3(SRC_LEN / 32, TRG_LEN / 32, BATCH), 256>>>(v_a, out);
}